// round 2
// baseline (speedup 1.0000x reference)
#include <cuda_runtime.h>
#include <math.h>

#define NDIM 2048
#define MSEQ 8192
#define G3   6144          // 3 * NDIM
#define NCTA 148
#define JMAX 14            // ceil(2048 / 148)
#define CACHE_ROWS 26      // rows of WhT cached in smem per CTA (26 * 8KB = 208KB)
#define SCAN_SMEM ((64 + CACHE_ROWS * NDIM) * sizeof(float))

// ---- device-global scratch (allocation-free per harness rules) ----
__device__ float g_gx[(size_t)MSEQ * G3];     // x @ Wx + b   (201 MB)
__device__ float g_WhT[(size_t)G3 * NDIM];    // Wh transposed (50 MB)
__device__ unsigned long long g_ticket;       // monotonic grid-barrier counter

// ============================================================
// Kernel 1: transpose Wh [2048, 6144] -> WhT [6144, 2048]
// ============================================================
__global__ void wh_transpose_kernel(const float* __restrict__ Wh) {
    __shared__ float tile[32][33];
    const int jb = blockIdx.x * 32;   // over 6144
    const int kb = blockIdx.y * 32;   // over 2048
    const int tx = threadIdx.x, ty = threadIdx.y;
    #pragma unroll
    for (int i = ty; i < 32; i += 8)
        tile[i][tx] = Wh[(size_t)(kb + i) * G3 + jb + tx];
    __syncthreads();
    #pragma unroll
    for (int i = ty; i < 32; i += 8)
        g_WhT[(size_t)(jb + i) * NDIM + kb + tx] = tile[tx][i];
}

// ============================================================
// Kernel 2: gx = x @ Wx + b   (8192x2048 @ 2048x6144)
// Classic 128x128x8 SGEMM, 256 threads, 8x8 per thread.
// ============================================================
__global__ __launch_bounds__(256) void gx_sgemm_kernel(
    const float* __restrict__ A,      // x  [M, K]
    const float* __restrict__ B,      // Wx [K, N]
    const float* __restrict__ bias)   // b  [N]
{
    __shared__ float As[8][128];
    __shared__ float Bs[8][128];
    const int tid  = threadIdx.x;
    const int tx   = tid & 15;        // 16 x 16 thread grid
    const int ty   = tid >> 4;
    const int row0 = blockIdx.y * 128;
    const int col0 = blockIdx.x * 128;
    const int a_row = tid >> 1, a_k = (tid & 1) * 4;
    const int b_k   = tid >> 5, b_col = (tid & 31) * 4;

    float acc[8][8];
    #pragma unroll
    for (int i = 0; i < 8; i++)
        #pragma unroll
        for (int j = 0; j < 8; j++) acc[i][j] = 0.f;

    const float* Aptr = A + (size_t)(row0 + a_row) * NDIM + a_k;
    const float* Bptr = B + (size_t)b_k * G3 + col0 + b_col;

    for (int k0 = 0; k0 < NDIM; k0 += 8) {
        float4 av = *(const float4*)(Aptr + k0);
        float4 bv = *(const float4*)(Bptr + (size_t)k0 * G3);
        As[a_k + 0][a_row] = av.x;
        As[a_k + 1][a_row] = av.y;
        As[a_k + 2][a_row] = av.z;
        As[a_k + 3][a_row] = av.w;
        *(float4*)&Bs[b_k][b_col] = bv;
        __syncthreads();
        #pragma unroll
        for (int kk = 0; kk < 8; kk++) {
            float ar[8], br[8];
            *(float4*)&ar[0] = *(const float4*)&As[kk][ty * 8];
            *(float4*)&ar[4] = *(const float4*)&As[kk][ty * 8 + 4];
            *(float4*)&br[0] = *(const float4*)&Bs[kk][tx * 8];
            *(float4*)&br[4] = *(const float4*)&Bs[kk][tx * 8 + 4];
            #pragma unroll
            for (int i = 0; i < 8; i++)
                #pragma unroll
                for (int j = 0; j < 8; j++)
                    acc[i][j] += ar[i] * br[j];
        }
        __syncthreads();
    }
    #pragma unroll
    for (int i = 0; i < 8; i++) {
        size_t m = (size_t)(row0 + ty * 8 + i);
        #pragma unroll
        for (int j = 0; j < 8; j += 4) {
            int n = col0 + tx * 8 + j;
            float4 o;
            o.x = acc[i][j + 0] + bias[n + 0];
            o.y = acc[i][j + 1] + bias[n + 1];
            o.z = acc[i][j + 2] + bias[n + 2];
            o.w = acc[i][j + 3] + bias[n + 3];
            *(float4*)&g_gx[m * G3 + n] = o;
        }
    }
}

// ============================================================
// Kernel 3: persistent GRU scan with chip-wide ticket barrier.
// 148 CTAs (1/SM, guaranteed co-resident: 208KB smem forces it).
// CTA c owns output channels j in [c*14, c*14+14) (clamped).
// Per step: gh rows = WhT rows {j, 2048+j, 4096+j}; 26 rows cached
// in smem (persistent across all 8192 steps), rest read from L2.
// h vector held in registers (16 float4 per lane).
// ============================================================
__global__ __launch_bounds__(256, 1) void gru_scan_kernel(float* __restrict__ out) {
    extern __shared__ float sh[];
    float* sh_gh   = sh;          // 64 floats (42 used + pad)
    float* sh_rows = sh + 64;     // CACHE_ROWS * 2048

    const int tid  = threadIdx.x;
    const int lane = tid & 31;
    const int warp = tid >> 5;    // 8 warps
    const int cta  = blockIdx.x;

    int j0 = cta * JMAX; if (j0 > NDIM) j0 = NDIM;
    int j1 = j0 + JMAX;  if (j1 > NDIM) j1 = NDIM;
    const int J = j1 - j0;
    const int R = 3 * J;
    const int CR = (R < CACHE_ROWS) ? R : CACHE_ROWS;

    // ---- preload cached rows of WhT into smem (once) ----
    for (int r = warp; r < CR; r += 8) {
        const int row_id = (r / J) * NDIM + j0 + (r % J);
        const float4* src = (const float4*)&g_WhT[(size_t)row_id * NDIM];
        float4* dst = (float4*)&sh_rows[(size_t)r * NDIM];
        for (int i = lane; i < NDIM / 4; i += 32) dst[i] = src[i];
    }
    __syncthreads();

    float4 h4[16];

    for (int t = 0; t < MSEQ; t++) {
        if (t > 0) {
            // load h_{t-1} into registers (each warp loads the full vector)
            const float4* hp = (const float4*)&out[(size_t)(t - 1) * NDIM];
            #pragma unroll
            for (int i = 0; i < 16; i++) h4[i] = hp[i * 32 + lane];

            // dot products: gh[row] = WhT[row] . h
            for (int r = warp; r < R; r += 8) {
                const float4* rp;
                if (r < CR) {
                    rp = (const float4*)&sh_rows[(size_t)r * NDIM];
                } else {
                    const int row_id = (r / J) * NDIM + j0 + (r % J);
                    rp = (const float4*)&g_WhT[(size_t)row_id * NDIM];
                }
                float acc = 0.f;
                #pragma unroll
                for (int i = 0; i < 16; i++) {
                    float4 w = rp[i * 32 + lane];
                    acc += w.x * h4[i].x + w.y * h4[i].y + w.z * h4[i].z + w.w * h4[i].w;
                }
                #pragma unroll
                for (int o = 16; o > 0; o >>= 1)
                    acc += __shfl_xor_sync(0xffffffffu, acc, o);
                if (lane == 0) sh_gh[r] = acc;
            }
        } else {
            if (tid < 64) sh_gh[tid] = 0.f;   // h0 = 0 -> gh = 0
        }
        __syncthreads();

        // ---- gate nonlinearities + state update for owned channels ----
        if (tid < J) {
            const int j = j0 + tid;
            const float ghz = sh_gh[tid];
            const float ghr = sh_gh[J + tid];
            const float ghn = sh_gh[2 * J + tid];
            const float* gx = &g_gx[(size_t)t * G3];
            const float z = 1.f / (1.f + expf(-(gx[j] + ghz)));
            const float r = 1.f / (1.f + expf(-(gx[NDIM + j] + ghr)));
            const float cand = tanhf(gx[2 * NDIM + j] + r * ghn);
            const float hp = (t > 0) ? out[(size_t)(t - 1) * NDIM + j] : 0.f;
            out[(size_t)t * NDIM + j] = (1.f - z) * hp + z * cand;
        }
        __threadfence();
        __syncthreads();

        // ---- chip-wide ticket barrier (monotonic; replay-safe) ----
        if (tid == 0) {
            unsigned long long tk = atomicAdd(&g_ticket, 1ULL);
            unsigned long long target = tk - (tk % (unsigned long long)NCTA)
                                        + (unsigned long long)NCTA;
            unsigned long long v;
            do {
                asm volatile("ld.acquire.gpu.global.u64 %0, [%1];"
                             : "=l"(v) : "l"(&g_ticket));
            } while (v < target);
        }
        __syncthreads();
    }
}

// ============================================================
extern "C" void kernel_launch(void* const* d_in, const int* in_sizes, int n_in,
                              void* d_out, int out_size) {
    const float* x  = (const float*)d_in[0];
    const float* Wx = (const float*)d_in[1];
    const float* Wh = (const float*)d_in[2];
    const float* b  = (const float*)d_in[3];
    float* out = (float*)d_out;

    cudaFuncSetAttribute(gru_scan_kernel,
                         cudaFuncAttributeMaxDynamicSharedMemorySize,
                         (int)SCAN_SMEM);

    // 1) WhT = Wh^T
    wh_transpose_kernel<<<dim3(G3 / 32, NDIM / 32), dim3(32, 8)>>>(Wh);
    // 2) gx = x @ Wx + b
    gx_sgemm_kernel<<<dim3(G3 / 128, MSEQ / 128), 256>>>(x, Wx, b);
    // 3) sequential GRU scan (persistent, grid-barriered)
    gru_scan_kernel<<<NCTA, 256, SCAN_SMEM>>>(out);
}

// round 7
// speedup vs baseline: 1.0439x; 1.0439x over previous
#include <cuda_runtime.h>
#include <math.h>

#define NDIM 2048
#define MSEQ 8192
#define G3   6144          // 3 * NDIM
#define NCTA 148
#define JMAX 14            // ceil(2048 / 148)
#define CACHE_ROWS 27      // rows of WhT cached in smem per CTA (27 * 8KB = 216KB)
#define SCAN_SMEM ((64 + NDIM + CACHE_ROWS * NDIM) * sizeof(float))  // 229,632 B

// ---- device-global scratch (allocation-free per harness rules) ----
__device__ float g_gx[(size_t)MSEQ * G3];     // x @ Wx + b   (201 MB)
__device__ float g_WhT[(size_t)G3 * NDIM];    // Wh transposed (50 MB)
__device__ unsigned long long g_ticket;       // monotonic grid-barrier counter

// ============================================================
// Kernel 1: transpose Wh [2048, 6144] -> WhT [6144, 2048]
// ============================================================
__global__ void wh_transpose_kernel(const float* __restrict__ Wh) {
    __shared__ float tile[32][33];
    const int jb = blockIdx.x * 32;   // over 6144
    const int kb = blockIdx.y * 32;   // over 2048
    const int tx = threadIdx.x, ty = threadIdx.y;
    #pragma unroll
    for (int i = ty; i < 32; i += 8)
        tile[i][tx] = Wh[(size_t)(kb + i) * G3 + jb + tx];
    __syncthreads();
    #pragma unroll
    for (int i = ty; i < 32; i += 8)
        g_WhT[(size_t)(jb + i) * NDIM + kb + tx] = tile[tx][i];
}

// ============================================================
// Kernel 2: gx = x @ Wx + b   (8192x2048 @ 2048x6144)
// Classic 128x128x8 SGEMM, 256 threads, 8x8 per thread.
// ============================================================
__global__ __launch_bounds__(256) void gx_sgemm_kernel(
    const float* __restrict__ A,      // x  [M, K]
    const float* __restrict__ B,      // Wx [K, N]
    const float* __restrict__ bias)   // b  [N]
{
    __shared__ float As[8][128];
    __shared__ float Bs[8][128];
    const int tid  = threadIdx.x;
    const int tx   = tid & 15;        // 16 x 16 thread grid
    const int ty   = tid >> 4;
    const int row0 = blockIdx.y * 128;
    const int col0 = blockIdx.x * 128;
    const int a_row = tid >> 1, a_k = (tid & 1) * 4;
    const int b_k   = tid >> 5, b_col = (tid & 31) * 4;

    float acc[8][8];
    #pragma unroll
    for (int i = 0; i < 8; i++)
        #pragma unroll
        for (int j = 0; j < 8; j++) acc[i][j] = 0.f;

    const float* Aptr = A + (size_t)(row0 + a_row) * NDIM + a_k;
    const float* Bptr = B + (size_t)b_k * G3 + col0 + b_col;

    for (int k0 = 0; k0 < NDIM; k0 += 8) {
        float4 av = *(const float4*)(Aptr + k0);
        float4 bv = *(const float4*)(Bptr + (size_t)k0 * G3);
        As[a_k + 0][a_row] = av.x;
        As[a_k + 1][a_row] = av.y;
        As[a_k + 2][a_row] = av.z;
        As[a_k + 3][a_row] = av.w;
        *(float4*)&Bs[b_k][b_col] = bv;
        __syncthreads();
        #pragma unroll
        for (int kk = 0; kk < 8; kk++) {
            float ar[8], br[8];
            *(float4*)&ar[0] = *(const float4*)&As[kk][ty * 8];
            *(float4*)&ar[4] = *(const float4*)&As[kk][ty * 8 + 4];
            *(float4*)&br[0] = *(const float4*)&Bs[kk][tx * 8];
            *(float4*)&br[4] = *(const float4*)&Bs[kk][tx * 8 + 4];
            #pragma unroll
            for (int i = 0; i < 8; i++)
                #pragma unroll
                for (int j = 0; j < 8; j++)
                    acc[i][j] += ar[i] * br[j];
        }
        __syncthreads();
    }
    #pragma unroll
    for (int i = 0; i < 8; i++) {
        size_t m = (size_t)(row0 + ty * 8 + i);
        #pragma unroll
        for (int j = 0; j < 8; j += 4) {
            int n = col0 + tx * 8 + j;
            float4 o;
            o.x = acc[i][j + 0] + bias[n + 0];
            o.y = acc[i][j + 1] + bias[n + 1];
            o.z = acc[i][j + 2] + bias[n + 2];
            o.w = acc[i][j + 3] + bias[n + 3];
            *(float4*)&g_gx[m * G3 + n] = o;
        }
    }
}

// ============================================================
// Kernel 3: persistent GRU scan with chip-wide ticket barrier.
// 148 CTAs (1/SM, forced by ~224KB smem). CTA c owns channels
// [c*14, c*14+14). 27 of its 42 WhT rows live in smem for the
// whole kernel; 15 come from L2 each step. h_{t-1} staged through
// smem once per CTA (8KB L2 instead of 64KB). gx prefetched with
// .cs before the matvec. Barrier = release-atomic ticket.
// ============================================================
__global__ __launch_bounds__(256, 1) void gru_scan_kernel(float* __restrict__ out) {
    extern __shared__ float sh[];
    float* sh_gh   = sh;                  // 64 floats (42 used)
    float* sh_h    = sh + 64;             // 2048 floats: staged h_{t-1}
    float* sh_rows = sh + 64 + NDIM;      // CACHE_ROWS * 2048

    const int tid  = threadIdx.x;
    const int lane = tid & 31;
    const int warp = tid >> 5;    // 8 warps
    const int cta  = blockIdx.x;

    int j0 = cta * JMAX; if (j0 > NDIM) j0 = NDIM;
    int j1 = j0 + JMAX;  if (j1 > NDIM) j1 = NDIM;
    const int J = j1 - j0;
    const int R = 3 * J;
    const int CR = (R < CACHE_ROWS) ? R : CACHE_ROWS;

    // ---- preload cached rows of WhT into smem (once) ----
    for (int r = warp; r < CR; r += 8) {
        const int row_id = (r / J) * NDIM + j0 + (r % J);
        const float4* src = (const float4*)&g_WhT[(size_t)row_id * NDIM];
        float4* dst = (float4*)&sh_rows[(size_t)r * NDIM];
        for (int i = lane; i < NDIM / 4; i += 32) dst[i] = src[i];
    }
    __syncthreads();

    float4 h4[16];

    for (int t = 0; t < MSEQ; t++) {
        // prefetch gx for this step (streaming: don't pollute L2 / WhT)
        float gxz = 0.f, gxr = 0.f, gxn = 0.f;
        if (tid < J) {
            const float* gx = g_gx + (size_t)t * G3;
            const int j = j0 + tid;
            gxz = __ldcs(gx + j);
            gxr = __ldcs(gx + NDIM + j);
            gxn = __ldcs(gx + 2 * NDIM + j);
        }

        if (t > 0) {
            // stage h_{t-1} into smem (one 8KB L2 read per CTA)
            const float4* hp4 = (const float4*)&out[(size_t)(t - 1) * NDIM];
            float4* shh4 = (float4*)sh_h;
            shh4[tid]       = hp4[tid];
            shh4[tid + 256] = hp4[tid + 256];
            __syncthreads();

            // broadcast h into per-warp registers
            #pragma unroll
            for (int i = 0; i < 16; i++) h4[i] = shh4[i * 32 + lane];

            // dot products: gh[row] = WhT[row] . h  (4 independent acc chains)
            for (int r = warp; r < R; r += 8) {
                const float4* rp;
                if (r < CR) {
                    rp = (const float4*)&sh_rows[(size_t)r * NDIM];
                } else {
                    const int row_id = (r / J) * NDIM + j0 + (r % J);
                    rp = (const float4*)&g_WhT[(size_t)row_id * NDIM];
                }
                float a0 = 0.f, a1 = 0.f, a2 = 0.f, a3 = 0.f;
                #pragma unroll
                for (int i = 0; i < 16; i += 4) {
                    float4 w0 = rp[(i + 0) * 32 + lane];
                    float4 w1 = rp[(i + 1) * 32 + lane];
                    float4 w2 = rp[(i + 2) * 32 + lane];
                    float4 w3 = rp[(i + 3) * 32 + lane];
                    a0 += w0.x * h4[i + 0].x + w0.y * h4[i + 0].y
                        + w0.z * h4[i + 0].z + w0.w * h4[i + 0].w;
                    a1 += w1.x * h4[i + 1].x + w1.y * h4[i + 1].y
                        + w1.z * h4[i + 1].z + w1.w * h4[i + 1].w;
                    a2 += w2.x * h4[i + 2].x + w2.y * h4[i + 2].y
                        + w2.z * h4[i + 2].z + w2.w * h4[i + 2].w;
                    a3 += w3.x * h4[i + 3].x + w3.y * h4[i + 3].y
                        + w3.z * h4[i + 3].z + w3.w * h4[i + 3].w;
                }
                float acc = (a0 + a1) + (a2 + a3);
                #pragma unroll
                for (int o = 16; o > 0; o >>= 1)
                    acc += __shfl_xor_sync(0xffffffffu, acc, o);
                if (lane == 0) sh_gh[r] = acc;
            }
        } else {
            if (tid < 64) sh_gh[tid] = 0.f;   // h0 = 0 -> gh = 0
        }
        __syncthreads();

        // ---- gate nonlinearities + state update for owned channels ----
        if (tid < J) {
            const int j = j0 + tid;
            const float ghz = sh_gh[tid];
            const float ghr = sh_gh[J + tid];
            const float ghn = sh_gh[2 * J + tid];
            const float z = 1.f / (1.f + expf(-(gxz + ghz)));
            const float r = 1.f / (1.f + expf(-(gxr + ghr)));
            const float cand = tanhf(gxn + r * ghn);
            const float hp = (t > 0) ? sh_h[j] : 0.f;
            out[(size_t)t * NDIM + j] = (1.f - z) * hp + z * cand;
        }
        __syncthreads();   // all out[t] writes ordered before tid0's release

        // ---- chip-wide ticket barrier (release atomic; replay-safe) ----
        if (tid == 0) {
            unsigned long long tk;
            asm volatile("atom.release.gpu.global.add.u64 %0, [%1], 1;"
                         : "=l"(tk) : "l"(&g_ticket) : "memory");
            unsigned long long target = tk - (tk % (unsigned long long)NCTA)
                                        + (unsigned long long)NCTA;
            unsigned long long v;
            do {
                asm volatile("ld.acquire.gpu.global.u64 %0, [%1];"
                             : "=l"(v) : "l"(&g_ticket) : "memory");
            } while (v < target);
        }
        __syncthreads();
    }
}

// ============================================================
extern "C" void kernel_launch(void* const* d_in, const int* in_sizes, int n_in,
                              void* d_out, int out_size) {
    const float* x  = (const float*)d_in[0];
    const float* Wx = (const float*)d_in[1];
    const float* Wh = (const float*)d_in[2];
    const float* b  = (const float*)d_in[3];
    float* out = (float*)d_out;

    cudaFuncSetAttribute(gru_scan_kernel,
                         cudaFuncAttributeMaxDynamicSharedMemorySize,
                         (int)SCAN_SMEM);

    // 1) WhT = Wh^T
    wh_transpose_kernel<<<dim3(G3 / 32, NDIM / 32), dim3(32, 8)>>>(Wh);
    // 2) gx = x @ Wx + b
    gx_sgemm_kernel<<<dim3(G3 / 128, MSEQ / 128), 256>>>(x, Wx, b);
    // 3) sequential GRU scan (persistent, grid-barriered)
    gru_scan_kernel<<<NCTA, 256, SCAN_SMEM>>>(out);
}